// round 5
// baseline (speedup 1.0000x reference)
#include <cuda_runtime.h>

// ---------------------------------------------------------------------------
// LSTMModel: 4-layer LSTM (H=50) over B=1024, T=512, IN=7, + FC(25) + FC(1).
// R5: k-packed fma.rn.f32x2 gate phase (0.75 instr/MAC), update fused into
// gate threads via in-quad shfl 4x4 transpose (one barrier per step).
// Thread 4u+p owns gate p*50+u; after transpose lane p updates batch row p.
// NB=4 -> 256 CTAs, 2 CTAs/SM. Warp 7 prefetches next-step input.
// ---------------------------------------------------------------------------

#define TT  512
#define BB  1024
#define HH  50
#define GG  200
#define NB  4
#define NCTA (BB / NB)    // 256
#define IN0 7
#define FC1 25

__device__ float g_bufA[TT * BB * HH];
__device__ float g_bufB[TT * BB * HH];
__device__ float g_xT[TT * BB * IN0];

__device__ __forceinline__ float sigmf(float x) {
    return __fdividef(1.0f, 1.0f + __expf(-x));
}
__device__ __forceinline__ float tanhfast(float x) {
    float e = __expf(2.0f * x);
    return 1.0f - __fdividef(2.0f, e + 1.0f);
}

#define FMA2(acc, w, h) \
    asm("fma.rn.f32x2 %0, %1, %2, %0;" : "+l"(acc) : "l"(w), "l"(h))
#define PACK2(out, lo, hi) \
    asm("mov.b64 %0, {%1, %2};" : "=l"(out) : "f"(lo), "f"(hi))
#define UNPACK2(lo, hi, in) \
    asm("mov.b64 {%0, %1}, %2;" : "=f"(lo), "=f"(hi) : "l"(in))

// ---------------------------------------------------------------------------
__global__ void transpose_x_kernel(const float* __restrict__ x) {
    int idx = blockIdx.x * blockDim.x + threadIdx.x;
    if (idx < BB * TT * IN0) {
        int k = idx % IN0;
        int t = (idx / IN0) % TT;
        int b = idx / (IN0 * TT);
        g_xT[(t * BB + b) * IN0 + k] = x[idx];
    }
}

// ---------------------------------------------------------------------------
template <int KIN>
__global__ void __launch_bounds__(256, 2) lstm_layer_kernel(
    int src, int dst,
    const float* __restrict__ Wih,   // [GG][KIN]
    const float* __restrict__ Whh,   // [GG][HH]
    const float* __restrict__ bih,
    const float* __restrict__ bhh)
{
    constexpr int K    = KIN + HH;          // 57 or 100
    constexpr int KQ   = (K + 3) / 4;       // 15 or 25
    constexpr int KPAD = KQ * 4;            // 60 or 100
    constexpr int PF   = (KIN * NB + 31) / 32;

    const float* __restrict__ in_seq =
        (src == 0) ? g_xT : ((src == 1) ? g_bufA : g_bufB);
    float* __restrict__ out_seq = (dst == 1) ? g_bufA : g_bufB;

    __shared__ __align__(16) float sh_in[2][NB][KPAD];  // [x | h | zero-pad]

    const int tid = threadIdx.x;
    const int b0  = blockIdx.x * NB;

    // thread 4u+p owns gate g = p*50 + u  (p = gate type: i,f,g,o)
    const int p  = tid & 3;
    const int u  = tid >> 2;
    const int uc = (u < HH) ? u : (HH - 1);   // clamp for dummy threads 200..223
    const int g  = p * HH + uc;
    const bool is_real = (tid < GG);

    // ---- packed weight row: (w_{2j}, w_{2j+1}) pairs over [Wih | Whh | 0-pad]
    unsigned long long wq[2 * KQ];
    float bg = 0.0f;
    if (tid < 224) {
#pragma unroll
        for (int q = 0; q < KQ; q++) {
#pragma unroll
            for (int h2 = 0; h2 < 2; h2++) {
                int k0 = 4 * q + 2 * h2;
                float w0 = (k0     < KIN) ? Wih[g * KIN + k0]
                         : (k0     < K  ) ? Whh[g * HH + (k0 - KIN)] : 0.0f;
                float w1 = (k0 + 1 < KIN) ? Wih[g * KIN + k0 + 1]
                         : (k0 + 1 < K  ) ? Whh[g * HH + (k0 + 1 - KIN)] : 0.0f;
                PACK2(wq[2 * q + h2], w0, w1);
            }
        }
        bg = bih[g] + bhh[g];
    }

    float creg = 0.0f;   // cell state for (unit u, batch row p)

    // ---- init: zero both buffers (h0 = 0, pad = 0), stage x(t=0) into buf 0
    for (int i = tid; i < 2 * NB * KPAD; i += 256)
        (&sh_in[0][0][0])[i] = 0.0f;
    __syncthreads();
    for (int i = tid; i < KIN * NB; i += 256) {
        int b = i % NB, k = i / NB;
        sh_in[0][b][k] = in_seq[(b0 + b) * KIN + k];
    }
    __syncthreads();

    int buf = 0;
    for (int t = 0; t < TT; t++) {
        const bool has_next = (t + 1 < TT);

        if (tid >= 224) {
            // ---- prefetch warp: load + park next-step x into other buffer
            if (has_next) {
                float pf[PF];
#pragma unroll
                for (int j = 0; j < PF; j++) {
                    int i = (tid - 224) + j * 32;
                    if (i < KIN * NB) {
                        int b = i % NB, k = i / NB;
                        pf[j] = in_seq[((t + 1) * BB + b0 + b) * KIN + k];
                    }
                }
#pragma unroll
                for (int j = 0; j < PF; j++) {
                    int i = (tid - 224) + j * 32;
                    if (i < KIN * NB) {
                        int b = i % NB, k = i / NB;
                        sh_in[buf ^ 1][b][k] = pf[j];
                    }
                }
            }
        } else {
            // ---- gate phase: acc2[b] = packed (even,odd) partial sums
            unsigned long long acc2[NB];
#pragma unroll
            for (int b = 0; b < NB; b++) acc2[b] = 0ull;
#pragma unroll
            for (int q = 0; q < KQ; q++) {
                unsigned long long w0 = wq[2 * q];
                unsigned long long w1 = wq[2 * q + 1];
#pragma unroll
                for (int b = 0; b < NB; b++) {
                    ulonglong2 hv = *(const ulonglong2*)&sh_in[buf][b][4 * q];
                    FMA2(acc2[b], w0, hv.x);
                    FMA2(acc2[b], w1, hv.y);
                }
            }
            float a[NB];
#pragma unroll
            for (int b = 0; b < NB; b++) {
                float lo, hi;
                UNPACK2(lo, hi, acc2[b]);
                a[b] = lo + hi + bg;
            }

            // ---- in-quad 4x4 transpose: after, a[e] = gate-type e of batch p
            {
                float tmp[NB];
#pragma unroll
                for (int e = 0; e < NB; e++)
                    tmp[e] = __shfl_xor_sync(0xffffffffu, a[e ^ 1], 1);
#pragma unroll
                for (int e = 0; e < NB; e++)
                    if ((e ^ p) & 1) a[e] = tmp[e];
#pragma unroll
                for (int e = 0; e < NB; e++)
                    tmp[e] = __shfl_xor_sync(0xffffffffu, a[e ^ 2], 2);
#pragma unroll
                for (int e = 0; e < NB; e++)
                    if ((e ^ p) & 2) a[e] = tmp[e];
            }

            // ---- fused update: this thread owns (unit u, batch row p)
            float ig = sigmf(a[0]);
            float fg = sigmf(a[1]);
            float gg = tanhfast(a[2]);
            float og = sigmf(a[3]);
            creg = fg * creg + ig * gg;
            float h = og * tanhfast(creg);
            if (is_real) {
                sh_in[buf ^ 1][p][KIN + u] = h;
                out_seq[(t * BB + b0 + p) * HH + u] = h;
            }
        }
        __syncthreads();
        buf ^= 1;
    }
}

// ---------------------------------------------------------------------------
__global__ void fc_head_kernel(int src,
                               const float* __restrict__ W1,
                               const float* __restrict__ b1,
                               const float* __restrict__ W2,
                               const float* __restrict__ b2,
                               float* __restrict__ out)
{
    const float* __restrict__ hseq = (src == 1) ? g_bufA : g_bufB;
    __shared__ float sW1[FC1 * HH];
    __shared__ float sW2[FC1];
    __shared__ float sb1[FC1];

    int tid = threadIdx.x;
    for (int i = tid; i < FC1 * HH; i += 256) sW1[i] = W1[i];
    if (tid < FC1) { sW2[tid] = W2[tid]; sb1[tid] = b1[tid]; }
    __syncthreads();

    int b = blockIdx.x * blockDim.x + tid;
    if (b < BB) {
        const float* h = &hseq[((TT - 1) * BB + b) * HH];
        float hreg[HH];
#pragma unroll
        for (int k = 0; k < HH; k++) hreg[k] = h[k];
        float o = b2[0];
#pragma unroll
        for (int j = 0; j < FC1; j++) {
            float a = sb1[j];
#pragma unroll
            for (int k = 0; k < HH; k++) a += sW1[j * HH + k] * hreg[k];
            o += sW2[j] * fmaxf(a, 0.0f);
        }
        out[b] = o;
    }
}

// ---------------------------------------------------------------------------
extern "C" void kernel_launch(void* const* d_in, const int* in_sizes, int n_in,
                              void* d_out, int out_size)
{
    const float* x    = (const float*)d_in[0];
    const float* Wih0 = (const float*)d_in[1];
    const float* Whh0 = (const float*)d_in[2];
    const float* bih0 = (const float*)d_in[3];
    const float* bhh0 = (const float*)d_in[4];
    const float* Wih1 = (const float*)d_in[5];
    const float* Whh1 = (const float*)d_in[6];
    const float* bih1 = (const float*)d_in[7];
    const float* bhh1 = (const float*)d_in[8];
    const float* Wih2 = (const float*)d_in[9];
    const float* Whh2 = (const float*)d_in[10];
    const float* bih2 = (const float*)d_in[11];
    const float* bhh2 = (const float*)d_in[12];
    const float* Wih3 = (const float*)d_in[13];
    const float* Whh3 = (const float*)d_in[14];
    const float* bih3 = (const float*)d_in[15];
    const float* bhh3 = (const float*)d_in[16];
    const float* W1   = (const float*)d_in[17];
    const float* b1   = (const float*)d_in[18];
    const float* W2   = (const float*)d_in[19];
    const float* b2   = (const float*)d_in[20];
    float* out = (float*)d_out;

    {
        int total = BB * TT * IN0;
        transpose_x_kernel<<<(total + 255) / 256, 256>>>(x);
    }
    lstm_layer_kernel<IN0><<<NCTA, 256>>>(0, 1, Wih0, Whh0, bih0, bhh0);
    lstm_layer_kernel<HH> <<<NCTA, 256>>>(1, 2, Wih1, Whh1, bih1, bhh1);
    lstm_layer_kernel<HH> <<<NCTA, 256>>>(2, 1, Wih2, Whh2, bih2, bhh2);
    lstm_layer_kernel<HH> <<<NCTA, 256>>>(1, 2, Wih3, Whh3, bih3, bhh3);
    fc_head_kernel<<<(BB + 255) / 256, 256>>>(2, W1, b1, W2, b2, out);
}

// round 6
// speedup vs baseline: 1.0178x; 1.0178x over previous
#include <cuda_runtime.h>

// ---------------------------------------------------------------------------
// LSTMModel: 4-layer LSTM (H=50) over B=1024, T=512, IN=7, + FC(25) + FC(1).
// R6: 512-thr CTAs, NB=8 rows, grid=128 (1 CTA/SM). Gate work split:
// warps 0..12, thread = (gate gid, k-half); batch-paired fma.rn.f32x2 over
// [k][b]-layout shared rows (2 LDS.128 + 1 dup-MOV + 4 FMA2 per k = 16 MACs).
// Halves reduced with shfl_xor(16). Warps 13..15 prefetch next-step x.
// Weights/regs per thread halved vs R4 -> ptxas slack for LDS hoisting.
// ---------------------------------------------------------------------------

#define TT  512
#define BB  1024
#define HH  50
#define GG  200
#define NB  8
#define NCTA (BB / NB)    // 128
#define IN0 7
#define FC1 25
#define NT  512

__device__ float g_bufA[TT * BB * HH];
__device__ float g_bufB[TT * BB * HH];
__device__ float g_xT[TT * BB * IN0];

__device__ __forceinline__ float sigmf(float x) {
    return __fdividef(1.0f, 1.0f + __expf(-x));
}
__device__ __forceinline__ float tanhfast(float x) {
    float e = __expf(2.0f * x);
    return 1.0f - __fdividef(2.0f, e + 1.0f);
}

#define FMA2(acc, w, h) \
    asm("fma.rn.f32x2 %0, %1, %2, %0;" : "+l"(acc) : "l"(w), "l"(h))
#define ADD2(out, a, b) \
    asm("add.rn.f32x2 %0, %1, %2;" : "=l"(out) : "l"(a), "l"(b))
#define DUP2(out, w) \
    asm("mov.b64 %0, {%1, %1};" : "=l"(out) : "f"(w))
#define UNPACK2(lo, hi, in) \
    asm("mov.b64 {%0, %1}, %2;" : "=f"(lo), "=f"(hi) : "l"(in))

// ---------------------------------------------------------------------------
__global__ void transpose_x_kernel(const float* __restrict__ x) {
    int idx = blockIdx.x * blockDim.x + threadIdx.x;
    if (idx < BB * TT * IN0) {
        int k = idx % IN0;
        int t = (idx / IN0) % TT;
        int b = idx / (IN0 * TT);
        g_xT[(t * BB + b) * IN0 + k] = x[idx];
    }
}

// ---------------------------------------------------------------------------
template <int KIN>
__global__ void __launch_bounds__(NT, 1) lstm_layer_kernel(
    int src, int dst,
    const float* __restrict__ Wih,   // [GG][KIN]
    const float* __restrict__ Whh,   // [GG][HH]
    const float* __restrict__ bih,
    const float* __restrict__ bhh)
{
    constexpr int K    = KIN + HH;            // 57 or 100
    constexpr int KH   = ((K + 3) / 4) * 2;   // per-half k count (even): 30 / 50
    constexpr int KPAD = 2 * KH;              // 60 / 100 (zero-padded tail)
    constexpr int PH   = KH / 2;              // pairs per half: 15 / 25
    constexpr int NPT  = NT - 416;            // 96 prefetch threads
    constexpr int PFN  = (KIN * NB + NPT - 1) / NPT;

    const float* __restrict__ in_seq =
        (src == 0) ? g_xT : ((src == 1) ? g_bufA : g_bufB);
    float* __restrict__ out_seq = (dst == 1) ? g_bufA : g_bufB;

    __shared__ __align__(16) float sh_in[2][KPAD][NB];  // rows: [x | h | 0-pad]
    __shared__ __align__(16) float sh_g[GG][NB];

    const int tid  = threadIdx.x;
    const int b0   = blockIdx.x * NB;
    const int w    = tid >> 5;
    const int lane = tid & 31;

    // gate mapping: warps 0..12; gid = w*16 + (lane&15), half = lane>>4
    const int gid_raw = w * 16 + (lane & 15);
    const int gid     = (gid_raw < GG) ? gid_raw : (GG - 1);   // clamp dups
    const bool g_live = (gid_raw < GG);
    const int half    = lane >> 4;
    const bool is_gate = (w <= 12);

    // ---- per-thread half-weights (k in [half*KH, half*KH+KH), zero-padded)
    float wreg[KH];
    float bg = 0.0f;
    if (is_gate) {
#pragma unroll
        for (int j = 0; j < KH; j++) {
            int k = half * KH + j;
            wreg[j] = (k < KIN) ? Wih[gid * KIN + k]
                    : (k < K  ) ? Whh[gid * HH + (k - KIN)] : 0.0f;
        }
        bg = bih[gid] + bhh[gid];
    }

    // ---- update-thread state: tid<200 owns (jj = tid>>2, rows {bu, bu+4})
    const int jj = tid >> 2;
    const int bu = tid & 3;
    float c0 = 0.0f, c1 = 0.0f;

    // ---- init: zero both buffers (h0 + pad), stage x(t=0) into buf 0
    for (int i = tid; i < 2 * KPAD * NB; i += NT)
        (&sh_in[0][0][0])[i] = 0.0f;
    __syncthreads();
    for (int i = tid; i < KIN * NB; i += NT) {
        int b = i % NB, k = i / NB;
        sh_in[0][k][b] = in_seq[(b0 + b) * KIN + k];
    }
    __syncthreads();

    int buf = 0;
    for (int t = 0; t < TT; t++) {
        const bool has_next = (t + 1 < TT);

        // ================= phase A =================
        if (is_gate) {
            // 8 independent packed accumulator chains: [bpair][k-parity]
            unsigned long long q[4][2];
#pragma unroll
            for (int j = 0; j < 4; j++) { q[j][0] = 0ull; q[j][1] = 0ull; }

            const int kbase = half * KH;
#pragma unroll
            for (int pp = 0; pp < PH; pp++) {
                const int k0 = kbase + 2 * pp;
                ulonglong2 vA0 = *(const ulonglong2*)&sh_in[buf][k0][0];
                ulonglong2 vB0 = *(const ulonglong2*)&sh_in[buf][k0][4];
                ulonglong2 vA1 = *(const ulonglong2*)&sh_in[buf][k0 + 1][0];
                ulonglong2 vB1 = *(const ulonglong2*)&sh_in[buf][k0 + 1][4];
                unsigned long long w0d, w1d;
                DUP2(w0d, wreg[2 * pp]);
                DUP2(w1d, wreg[2 * pp + 1]);
                FMA2(q[0][0], w0d, vA0.x);
                FMA2(q[1][0], w0d, vA0.y);
                FMA2(q[2][0], w0d, vB0.x);
                FMA2(q[3][0], w0d, vB0.y);
                FMA2(q[0][1], w1d, vA1.x);
                FMA2(q[1][1], w1d, vA1.y);
                FMA2(q[2][1], w1d, vB1.x);
                FMA2(q[3][1], w1d, vB1.y);
            }

            // merge parities, unpack, cross-half shfl reduce
            float s[NB];
#pragma unroll
            for (int j = 0; j < 4; j++) {
                unsigned long long m;
                ADD2(m, q[j][0], q[j][1]);
                UNPACK2(s[2 * j], s[2 * j + 1], m);
            }
#pragma unroll
            for (int j = 0; j < NB; j++)
                s[j] += __shfl_xor_sync(0xffffffffu, s[j], 16);

            if (g_live && half == 0) {
#pragma unroll
                for (int j = 0; j < NB; j++) s[j] += bg;
                *(float4*)&sh_g[gid][0] = make_float4(s[0], s[1], s[2], s[3]);
                *(float4*)&sh_g[gid][4] = make_float4(s[4], s[5], s[6], s[7]);
            }
        } else if (has_next) {
            // prefetch warp group: load + park next-step x into other buffer
            float pf[PFN];
#pragma unroll
            for (int j = 0; j < PFN; j++) {
                int i = (tid - 416) + j * NPT;
                if (i < KIN * NB) {
                    int b = i % NB, k = i / NB;
                    pf[j] = in_seq[((t + 1) * BB + b0 + b) * KIN + k];
                }
            }
#pragma unroll
            for (int j = 0; j < PFN; j++) {
                int i = (tid - 416) + j * NPT;
                if (i < KIN * NB) {
                    int b = i % NB, k = i / NB;
                    sh_in[buf ^ 1][k][b] = pf[j];
                }
            }
        }
        __syncthreads();

        // ================= phase B: update (tid < 200, 2 rows each) =========
        if (tid < GG) {
#pragma unroll
            for (int qq = 0; qq < 2; qq++) {
                int b = bu + 4 * qq;
                float ig = sigmf(sh_g[jj][b]);
                float fg = sigmf(sh_g[HH + jj][b]);
                float gg = tanhfast(sh_g[2 * HH + jj][b]);
                float og = sigmf(sh_g[3 * HH + jj][b]);
                float& c = qq ? c1 : c0;
                c = fg * c + ig * gg;
                float h = og * tanhfast(c);
                sh_in[buf ^ 1][KIN + jj][b] = h;
                out_seq[(t * BB + b0 + b) * HH + jj] = h;
            }
        }
        __syncthreads();
        buf ^= 1;
    }
}

// ---------------------------------------------------------------------------
__global__ void fc_head_kernel(int src,
                               const float* __restrict__ W1,
                               const float* __restrict__ b1,
                               const float* __restrict__ W2,
                               const float* __restrict__ b2,
                               float* __restrict__ out)
{
    const float* __restrict__ hseq = (src == 1) ? g_bufA : g_bufB;
    __shared__ float sW1[FC1 * HH];
    __shared__ float sW2[FC1];
    __shared__ float sb1[FC1];

    int tid = threadIdx.x;
    for (int i = tid; i < FC1 * HH; i += 256) sW1[i] = W1[i];
    if (tid < FC1) { sW2[tid] = W2[tid]; sb1[tid] = b1[tid]; }
    __syncthreads();

    int b = blockIdx.x * blockDim.x + tid;
    if (b < BB) {
        const float* h = &hseq[((TT - 1) * BB + b) * HH];
        float hreg[HH];
#pragma unroll
        for (int k = 0; k < HH; k++) hreg[k] = h[k];
        float o = b2[0];
#pragma unroll
        for (int j = 0; j < FC1; j++) {
            float a = sb1[j];
#pragma unroll
            for (int k = 0; k < HH; k++) a += sW1[j * HH + k] * hreg[k];
            o += sW2[j] * fmaxf(a, 0.0f);
        }
        out[b] = o;
    }
}

// ---------------------------------------------------------------------------
extern "C" void kernel_launch(void* const* d_in, const int* in_sizes, int n_in,
                              void* d_out, int out_size)
{
    const float* x    = (const float*)d_in[0];
    const float* Wih0 = (const float*)d_in[1];
    const float* Whh0 = (const float*)d_in[2];
    const float* bih0 = (const float*)d_in[3];
    const float* bhh0 = (const float*)d_in[4];
    const float* Wih1 = (const float*)d_in[5];
    const float* Whh1 = (const float*)d_in[6];
    const float* bih1 = (const float*)d_in[7];
    const float* bhh1 = (const float*)d_in[8];
    const float* Wih2 = (const float*)d_in[9];
    const float* Whh2 = (const float*)d_in[10];
    const float* bih2 = (const float*)d_in[11];
    const float* bhh2 = (const float*)d_in[12];
    const float* Wih3 = (const float*)d_in[13];
    const float* Whh3 = (const float*)d_in[14];
    const float* bih3 = (const float*)d_in[15];
    const float* bhh3 = (const float*)d_in[16];
    const float* W1   = (const float*)d_in[17];
    const float* b1   = (const float*)d_in[18];
    const float* W2   = (const float*)d_in[19];
    const float* b2   = (const float*)d_in[20];
    float* out = (float*)d_out;

    {
        int total = BB * TT * IN0;
        transpose_x_kernel<<<(total + 255) / 256, 256>>>(x);
    }
    lstm_layer_kernel<IN0><<<NCTA, NT>>>(0, 1, Wih0, Whh0, bih0, bhh0);
    lstm_layer_kernel<HH> <<<NCTA, NT>>>(1, 2, Wih1, Whh1, bih1, bhh1);
    lstm_layer_kernel<HH> <<<NCTA, NT>>>(2, 1, Wih2, Whh2, bih2, bhh2);
    lstm_layer_kernel<HH> <<<NCTA, NT>>>(1, 2, Wih3, Whh3, bih3, bhh3);
    fc_head_kernel<<<(BB + 255) / 256, 256>>>(2, W1, b1, W2, b2, out);
}